// round 8
// baseline (speedup 1.0000x reference)
#include <cuda_runtime.h>
#include <cuda_bf16.h>
#include <math.h>

#define HD 64
#define NE 1024
#define TT 4096
#define NB 4
#define BT (NB*TT)

typedef unsigned long long u64;
typedef unsigned int u32;

// ---- device scratch (no allocs allowed) ----
// W^T bf16 hi/lo, chunk-major + SW128-pre-swizzled: [chunk 16][n' 192][k 64]
__device__ __align__(128) __nv_bfloat16 g_wth[16*192*64];
__device__ __align__(128) __nv_bfloat16 g_wtl[16*192*64];
// q/k blocked: [tile 256][s 64][h 64] bf16, swizzled; v transposed: [tile][h 64][s 64]
__device__ __align__(128) __nv_bfloat16 g_qh[BT*HD];
__device__ __align__(128) __nv_bfloat16 g_ql[BT*HD];
__device__ __align__(128) __nv_bfloat16 g_kh[BT*HD];
__device__ __align__(128) __nv_bfloat16 g_kl[BT*HD];
__device__ __align__(128) __nv_bfloat16 g_vth[BT*HD];
__device__ __align__(128) __nv_bfloat16 g_vtl[BT*HD];

// ---------------- PTX helpers ----------------
__device__ __forceinline__ u32 s2u(const void* p) {
    return (u32)__cvta_generic_to_shared(p);
}
__device__ __forceinline__ void mbar_init(u32 mb, u32 cnt) {
    asm volatile("mbarrier.init.shared.b64 [%0], %1;" :: "r"(mb), "r"(cnt) : "memory");
}
__device__ __forceinline__ void mbar_expect(u32 mb, u32 tx) {
    asm volatile("mbarrier.arrive.expect_tx.shared.b64 _, [%0], %1;" :: "r"(mb), "r"(tx) : "memory");
}
__device__ __forceinline__ void bulk_g2s(u32 dst, const void* src, u32 bytes, u32 mb) {
    asm volatile("cp.async.bulk.shared::cluster.global.mbarrier::complete_tx::bytes [%0], [%1], %2, [%3];"
                 :: "r"(dst), "l"(src), "r"(bytes), "r"(mb) : "memory");
}
__device__ __forceinline__ void waitpar(u32 mb, u32 ph) {
    asm volatile(
        "{\n\t.reg .pred P;\n"
        "W%=:\n\t"
        "mbarrier.try_wait.parity.acquire.cta.shared::cta.b64 P, [%0], %1, 0x989680;\n\t"
        "@P bra D%=;\n\t"
        "bra W%=;\n"
        "D%=:\n\t}"
        :: "r"(mb), "r"(ph) : "memory");
}
// bf16x2 pack: low half = lo param, high half = hi param
__device__ __forceinline__ u32 bf2(float lo, float hi) {
    u32 d; asm("cvt.rn.bf16x2.f32 %0, %1, %2;" : "=r"(d) : "f"(hi), "f"(lo));
    return d;
}
__device__ __forceinline__ float lo16f(u32 h) { return __uint_as_float(h << 16); }
__device__ __forceinline__ float hi16f(u32 h) { return __uint_as_float(h & 0xFFFF0000u); }
__device__ __forceinline__ void ldsm4(u32* r, u32 addr) {
    asm volatile("ldmatrix.sync.aligned.m8n8.x4.shared.b16 {%0,%1,%2,%3}, [%4];"
        : "=r"(r[0]), "=r"(r[1]), "=r"(r[2]), "=r"(r[3]) : "r"(addr));
}
__device__ __forceinline__ void ldsm2(u32* r, u32 addr) {
    asm volatile("ldmatrix.sync.aligned.m8n8.x2.shared.b16 {%0,%1}, [%2];"
        : "=r"(r[0]), "=r"(r[1]) : "r"(addr));
}
__device__ __forceinline__ void mma_bf16(float* c, const u32* a, const u32* b) {
    asm volatile("mma.sync.aligned.m16n8k16.row.col.f32.bf16.bf16.f32 "
        "{%0,%1,%2,%3}, {%4,%5,%6,%7}, {%8,%9}, {%0,%1,%2,%3};"
        : "+f"(c[0]), "+f"(c[1]), "+f"(c[2]), "+f"(c[3])
        : "r"(a[0]), "r"(a[1]), "r"(a[2]), "r"(a[3]), "r"(b[0]), "r"(b[1]));
}
__device__ __forceinline__ u32 abyte(int row, int q) {
    return (u32)(row * 128 + (((q) ^ (row & 7)) << 4));
}

// ---------------------------------------------------------------------------
// Kernel 0: W transpose + bf16 hi/lo + chunk-major SW128 pre-swizzle.
// ---------------------------------------------------------------------------
__global__ void wconv_kernel(const float* __restrict__ Wk,
                             const float* __restrict__ Wq,
                             const float* __restrict__ Wv)
{
    int np  = blockIdx.x;            // 0..191
    int mat = np >> 6;
    int n   = np & 63;
    const float* W = (mat == 0) ? Wk : (mat == 1) ? Wq : Wv;
    char* dh = (char*)g_wth;
    char* dl = (char*)g_wtl;
    int k = blockIdx.y * 256 + threadIdx.x;
    float v = W[k * HD + n];
    __nv_bfloat16 h = __float2bfloat16(v);
    float hf = __bfloat162float(h);
    __nv_bfloat16 l = __float2bfloat16(v - hf);
    int ch = k >> 6, kc = k & 63;
    u32 off = (u32)np * 128 + kc * 2;
    u32 sw  = off ^ ((np & 7) * 16);
    *(__nv_bfloat16*)(dh + ch * 24576 + sw) = h;
    *(__nv_bfloat16*)(dl + ch * 24576 + sw) = l;
}

// ---------------------------------------------------------------------------
// Kernel 1: QKV projection via mma.sync bf16 hi/lo.
// CTA: 64 rows x 192 cols, 256 threads, 8 warps (4M x 2N), warp 16x96.
// W single-buffered (co-resident CTA hides latency); x LDG->cvt->STS pipelined.
// smem ~64KB -> 2 CTAs/SM; grid 256 fills all SMs.
// ---------------------------------------------------------------------------
#define NCH 16
#define Q_XH 128
#define Q_XL (128 + 8192)
#define Q_W  (128 + 16384)
#define P_SMEM (Q_W + 49152)        // 65664

__global__ __launch_bounds__(256, 2) void proj_kernel(const float* __restrict__ x)
{
    extern __shared__ char sm[];
    const u32 smb = s2u(sm);
    const int tid  = threadIdx.x;
    const int warp = tid >> 5;
    const int lane = tid & 31;
    const int wm   = warp >> 1;      // 0..3 : 16-row group
    const int wn   = warp & 1;       // 0..1 : 96-col group
    const int row0 = blockIdx.x * 64;

    const u32 mb0 = smb;
    if (tid == 0) mbar_init(mb0, 1);
    __syncthreads();

    const char* wh_g = (const char*)g_wth;
    const char* wl_g = (const char*)g_wtl;

    if (tid == 0) {
        mbar_expect(mb0, 49152);
        bulk_g2s(smb + Q_W,         wh_g, 24576, mb0);
        bulk_g2s(smb + Q_W + 24576, wl_g, 24576, mb0);
    }

    float C[12][4];
    #pragma unroll
    for (int nt = 0; nt < 12; nt++)
        #pragma unroll
        for (int i = 0; i < 4; i++) C[nt][i] = 0.f;

    // stage x chunk 0: 64 rows x 64 k
    float4 xr[4];
    #pragma unroll
    for (int i = 0; i < 4; i++) {
        int idx = tid + i * 256;            // 0..1023
        int r = idx >> 4, c4 = idx & 15;
        xr[i] = *(const float4*)&x[(size_t)(row0 + r) * NE + c4 * 4];
    }
    #pragma unroll
    for (int i = 0; i < 4; i++) {
        int idx = tid + i * 256;
        int r = idx >> 4, c4 = idx & 15;
        float4 v = xr[i];
        u32 h01 = bf2(v.x, v.y);
        u32 h23 = bf2(v.z, v.w);
        u32 l01 = bf2(v.x - lo16f(h01), v.y - hi16f(h01));
        u32 l23 = bf2(v.z - lo16f(h23), v.w - hi16f(h23));
        u32 off = (u32)r * 128 + c4 * 8;
        u32 sw  = off ^ ((r & 7) * 16);
        *(u64*)(sm + Q_XH + sw) = (u64)h01 | ((u64)h23 << 32);
        *(u64*)(sm + Q_XL + sw) = (u64)l01 | ((u64)l23 << 32);
    }
    __syncthreads();

    u32 ph = 0;
    const int rowA0 = wm * 16 + (lane & 15);
    const int qselA = lane >> 4;
    const int nrow0 = wn * 96 + (lane & 7);
    const int gB    = (lane >> 3) & 1;

    for (int c = 0; c < NCH; c++) {
        if (c < NCH - 1) {
            const int kk = (c + 1) * 64;
            #pragma unroll
            for (int i = 0; i < 4; i++) {
                int idx = tid + i * 256;
                int r = idx >> 4, c4 = idx & 15;
                xr[i] = *(const float4*)&x[(size_t)(row0 + r) * NE + kk + c4 * 4];
            }
        }

        waitpar(mb0, ph); ph ^= 1;
        const u32 wbase = smb + Q_W;

        #pragma unroll
        for (int ks = 0; ks < 4; ks++) {
            u32 ah[4], al[4];
            u32 ba = abyte(rowA0, ks * 2 + qselA);
            ldsm4(ah, smb + Q_XH + ba);
            ldsm4(al, smb + Q_XL + ba);
            #pragma unroll
            for (int nt = 0; nt < 12; nt++) {
                u32 bh[2], bl[2];
                u32 bb = abyte(nrow0 + nt * 8, ks * 2 + gB);
                ldsm2(bh, wbase + bb);
                ldsm2(bl, wbase + 24576 + bb);
                mma_bf16(C[nt], ah, bh);
                mma_bf16(C[nt], ah, bl);
                mma_bf16(C[nt], al, bh);
            }
        }
        __syncthreads();   // W buffer + x buffer consumed

        if (c < NCH - 1) {
            if (tid == 0) {
                mbar_expect(mb0, 49152);
                bulk_g2s(smb + Q_W,         wh_g + (size_t)(c + 1) * 24576, 24576, mb0);
                bulk_g2s(smb + Q_W + 24576, wl_g + (size_t)(c + 1) * 24576, 24576, mb0);
            }
            #pragma unroll
            for (int i = 0; i < 4; i++) {
                int idx = tid + i * 256;
                int r = idx >> 4, c4 = idx & 15;
                float4 v = xr[i];
                u32 h01 = bf2(v.x, v.y);
                u32 h23 = bf2(v.z, v.w);
                u32 l01 = bf2(v.x - lo16f(h01), v.y - hi16f(h01));
                u32 l23 = bf2(v.z - lo16f(h23), v.w - hi16f(h23));
                u32 off = (u32)r * 128 + c4 * 8;
                u32 sw  = off ^ ((r & 7) * 16);
                *(u64*)(sm + Q_XH + sw) = (u64)h01 | ((u64)h23 << 32);
                *(u64*)(sm + Q_XL + sw) = (u64)l01 | ((u64)l23 << 32);
            }
            __syncthreads();
        }
    }

    // ---- epilogue: q/k blocked [tile][s][h], v^T [tile][h][s], hi/lo bf16 ----
    {
        int r_lo = row0 + wm * 16 + (lane >> 2);   // and r_lo+8, same 64-tile
        size_t tb = (size_t)(r_lo >> 6) * 8192;
        int s0 = r_lo & 63, s1 = s0 + 8;
        #pragma unroll
        for (int nt = 0; nt < 12; nt++) {
            int col = wn * 96 + nt * 8 + 2 * (lane & 3);
            int mat = col >> 6;
            int h   = col & 63;
            float sc = (mat == 1) ? 0.03125f : 1.0f;   // 1024^-0.5 folded into q
            float v0 = C[nt][0] * sc, v1 = C[nt][1] * sc;
            float v2 = C[nt][2] * sc, v3 = C[nt][3] * sc;
            if (mat != 2) {
                char* dh = (mat == 0) ? (char*)g_kh : (char*)g_qh;
                char* dl = (mat == 0) ? (char*)g_kl : (char*)g_ql;
                u32 h01 = bf2(v0, v1);
                u32 l01 = bf2(v0 - lo16f(h01), v1 - hi16f(h01));
                u32 h23 = bf2(v2, v3);
                u32 l23 = bf2(v2 - lo16f(h23), v3 - hi16f(h23));
                size_t a0 = tb + s0 * 128 + ((((h >> 3) ^ (s0 & 7)) << 4) + (h & 7) * 2);
                size_t a1 = tb + s1 * 128 + ((((h >> 3) ^ (s1 & 7)) << 4) + (h & 7) * 2);
                *(u32*)(dh + a0) = h01;  *(u32*)(dl + a0) = l01;
                *(u32*)(dh + a1) = h23;  *(u32*)(dl + a1) = l23;
            } else {
                char* dh = (char*)g_vth;
                char* dl = (char*)g_vtl;
                float vv[4] = {v0, v1, v2, v3};
                #pragma unroll
                for (int e = 0; e < 4; e++) {
                    int hh = h + (e & 1);
                    int ss = (e < 2) ? s0 : s1;
                    __nv_bfloat16 bh = __float2bfloat16(vv[e]);
                    __nv_bfloat16 bl = __float2bfloat16(vv[e] - __bfloat162float(bh));
                    size_t a = tb + hh * 128 + ((((ss >> 3) ^ (hh & 7)) << 4) + (ss & 7) * 2);
                    *(__nv_bfloat16*)(dh + a) = bh;
                    *(__nv_bfloat16*)(dl + a) = bl;
                }
            }
        }
    }
}

// ---------------------------------------------------------------------------
// Kernel 2: causal flash attention via mma.sync bf16 hi/lo, software-pipelined:
// S for stage gi+1 is issued BEFORE softmax(gi) so HMMAs drain during the
// exp/shuffle chain. Double-buffered S accumulators (sA/sB).
// CTA = 4 warps, tile M=64, stages BK=64 double-buffered via cp.async.bulk.
// CTA processes tile pair (tq, 63-tq): uniform 65 stages.
// ---------------------------------------------------------------------------
#define A_QH  128
#define A_QL  (128 + 8192)
#define A_ST  (128 + 16384)
#define A_STG 32768
#define A_SMEM (A_ST + 2*A_STG)      // 82048

struct AttnCtx {
    u32 smb;
    u32 mb[2];
    u32 ph[2];
    int browB, bgB;
    int n_iter, tq;
    float m0, m1, l0, l1;
};

__device__ __forceinline__ void compute_S(AttnCtx& cx, float (&dst)[8][4],
                                          const u32 (&qfh)[4][4], const u32 (&qfl)[4][4],
                                          int si, int lane)
{
    const u32 kb = cx.smb + A_ST + (si & 1) * A_STG;
    #pragma unroll
    for (int nt = 0; nt < 8; nt++)
        #pragma unroll
        for (int i = 0; i < 4; i++) dst[nt][i] = 0.f;
    #pragma unroll
    for (int ks = 0; ks < 4; ks++) {
        #pragma unroll
        for (int ntp = 0; ntp < 4; ntp++) {
            int nr = ntp * 16 + cx.browB;
            u32 off = (u32)(nr * 128 + (((ks * 2 + cx.bgB) ^ (nr & 7)) << 4));
            u32 kh4[4], kl4[4];
            ldsm4(kh4, kb + off);
            ldsm4(kl4, kb + 8192 + off);
            mma_bf16(dst[2*ntp],   qfh[ks], kh4);
            mma_bf16(dst[2*ntp],   qfh[ks], kl4);
            mma_bf16(dst[2*ntp],   qfl[ks], kh4);
            mma_bf16(dst[2*ntp+1], qfh[ks], kh4 + 2);
            mma_bf16(dst[2*ntp+1], qfh[ks], kl4 + 2);
            mma_bf16(dst[2*ntp+1], qfl[ks], kh4 + 2);
        }
    }
    if (si == cx.tq) {   // causal mask on diagonal stage
        int rl = (threadIdx.x >> 5) * 16 + (lane >> 2);
        #pragma unroll
        for (int nt = 0; nt < 8; nt++) {
            int cl = nt * 8 + 2 * (lane & 3);
            if (cl     > rl)     dst[nt][0] = -1e30f;
            if (cl + 1 > rl)     dst[nt][1] = -1e30f;
            if (cl     > rl + 8) dst[nt][2] = -1e30f;
            if (cl + 1 > rl + 8) dst[nt][3] = -1e30f;
        }
    }
}

__device__ __forceinline__ void stage_body(AttnCtx& cx, float (&cur)[8][4], float (&nxt)[8][4],
                                           float (&o)[8][4],
                                           const u32 (&qfh)[4][4], const u32 (&qfl)[4][4],
                                           int gi, int lane, int tid,
                                           const char* kh_g, const char* kl_g,
                                           const char* vth_g, const char* vtl_g,
                                           size_t tbase)
{
    const int si = gi + 1;
    if (si < cx.n_iter) {
        const int s = si & 1;
        waitpar(cx.mb[s], cx.ph[s]); cx.ph[s] ^= 1;
        compute_S(cx, nxt, qfh, qfl, si, lane);
    }

    // ---- online softmax on cur ----
    float mx0 = cur[0][0], mx1 = cur[0][2];
    #pragma unroll
    for (int nt = 0; nt < 8; nt++) {
        mx0 = fmaxf(mx0, fmaxf(cur[nt][0], cur[nt][1]));
        mx1 = fmaxf(mx1, fmaxf(cur[nt][2], cur[nt][3]));
    }
    mx0 = fmaxf(mx0, __shfl_xor_sync(0xffffffffu, mx0, 1));
    mx0 = fmaxf(mx0, __shfl_xor_sync(0xffffffffu, mx0, 2));
    mx1 = fmaxf(mx1, __shfl_xor_sync(0xffffffffu, mx1, 1));
    mx1 = fmaxf(mx1, __shfl_xor_sync(0xffffffffu, mx1, 2));
    float mn0 = fmaxf(cx.m0, mx0), mn1 = fmaxf(cx.m1, mx1);
    float sc0 = __expf(cx.m0 - mn0), sc1 = __expf(cx.m1 - mn1);
    float sum0 = 0.f, sum1 = 0.f;
    #pragma unroll
    for (int nt = 0; nt < 8; nt++) {
        cur[nt][0] = __expf(cur[nt][0] - mn0);
        cur[nt][1] = __expf(cur[nt][1] - mn0);
        cur[nt][2] = __expf(cur[nt][2] - mn1);
        cur[nt][3] = __expf(cur[nt][3] - mn1);
        sum0 += cur[nt][0] + cur[nt][1];
        sum1 += cur[nt][2] + cur[nt][3];
    }
    sum0 += __shfl_xor_sync(0xffffffffu, sum0, 1);
    sum0 += __shfl_xor_sync(0xffffffffu, sum0, 2);
    sum1 += __shfl_xor_sync(0xffffffffu, sum1, 1);
    sum1 += __shfl_xor_sync(0xffffffffu, sum1, 2);
    cx.l0 = cx.l0 * sc0 + sum0;  cx.l1 = cx.l1 * sc1 + sum1;
    cx.m0 = mn0;  cx.m1 = mn1;
    #pragma unroll
    for (int nt = 0; nt < 8; nt++) {
        o[nt][0] *= sc0;  o[nt][1] *= sc0;
        o[nt][2] *= sc1;  o[nt][3] *= sc1;
    }

    // ---- O += P V ----
    const u32 vb = cx.smb + A_ST + (gi & 1) * A_STG + 16384;
    #pragma unroll
    for (int kt = 0; kt < 4; kt++) {
        const float* sA = cur[2*kt];
        const float* sB = cur[2*kt+1];
        u32 pH[4], pL[4];
        pH[0] = bf2(sA[0], sA[1]);
        pH[1] = bf2(sA[2], sA[3]);
        pH[2] = bf2(sB[0], sB[1]);
        pH[3] = bf2(sB[2], sB[3]);
        pL[0] = bf2(sA[0] - lo16f(pH[0]), sA[1] - hi16f(pH[0]));
        pL[1] = bf2(sA[2] - lo16f(pH[1]), sA[3] - hi16f(pH[1]));
        pL[2] = bf2(sB[0] - lo16f(pH[2]), sB[1] - hi16f(pH[2]));
        pL[3] = bf2(sB[2] - lo16f(pH[3]), sB[3] - hi16f(pH[3]));
        #pragma unroll
        for (int ntp = 0; ntp < 4; ntp++) {
            int nr = ntp * 16 + cx.browB;
            u32 off = (u32)(nr * 128 + (((kt * 2 + cx.bgB) ^ (nr & 7)) << 4));
            u32 vh4[4], vl4[4];
            ldsm4(vh4, vb + off);
            ldsm4(vl4, vb + 8192 + off);
            mma_bf16(o[2*ntp],   pH, vh4);
            mma_bf16(o[2*ntp],   pH, vl4);
            mma_bf16(o[2*ntp],   pL, vh4);
            mma_bf16(o[2*ntp+1], pH, vh4 + 2);
            mma_bf16(o[2*ntp+1], pH, vl4 + 2);
            mma_bf16(o[2*ntp+1], pL, vh4 + 2);
        }
    }

    __syncthreads();
    if (tid == 0 && gi + 2 < cx.n_iter) {
        const size_t tn = tbase + (size_t)(gi + 2) * 8192;
        const int s = gi & 1;
        u32 d = cx.smb + A_ST + s * A_STG;
        mbar_expect(cx.mb[s], A_STG);
        bulk_g2s(d,         kh_g  + tn, 8192, cx.mb[s]);
        bulk_g2s(d + 8192,  kl_g  + tn, 8192, cx.mb[s]);
        bulk_g2s(d + 16384, vth_g + tn, 8192, cx.mb[s]);
        bulk_g2s(d + 24576, vtl_g + tn, 8192, cx.mb[s]);
    }
}

__global__ __launch_bounds__(128) void attn2_kernel(float* __restrict__ out)
{
    extern __shared__ char sm[];
    const u32 smb = s2u(sm);
    const int tid  = threadIdx.x;
    const int warp = tid >> 5;
    const int lane = tid & 31;
    const int b    = blockIdx.y;
    const int pidx = blockIdx.x;      // 0..31

    AttnCtx cx;
    cx.smb = smb;
    cx.mb[0] = smb;  cx.mb[1] = smb + 8;
    cx.ph[0] = 0;    cx.ph[1] = 0;
    cx.browB = ((lane >> 4) << 3) + (lane & 7);
    cx.bgB   = (lane >> 3) & 1;

    if (tid == 0) { mbar_init(cx.mb[0], 1); mbar_init(cx.mb[1], 1); }
    __syncthreads();

    const int lrowA = warp * 16 + (lane & 15);
    const int lqA   = lane >> 4;

    const char* qh_g  = (const char*)g_qh;
    const char* ql_g  = (const char*)g_ql;
    const char* kh_g  = (const char*)g_kh;
    const char* kl_g  = (const char*)g_kl;
    const char* vth_g = (const char*)g_vth;
    const char* vtl_g = (const char*)g_vtl;

    for (int ti = 0; ti < 2; ti++) {
        const int tq     = ti ? (63 - pidx) : pidx;
        cx.tq     = tq;
        cx.n_iter = tq + 1;
        const size_t tgq   = (size_t)(b * 64 + tq) * 8192;
        const size_t tbase = (size_t)(b * 64) * 8192;

        __syncthreads();
        if (tid == 0) {
            mbar_expect(cx.mb[0], 16384 + A_STG);
            bulk_g2s(smb + A_QH, qh_g + tgq, 8192, cx.mb[0]);
            bulk_g2s(smb + A_QL, ql_g + tgq, 8192, cx.mb[0]);
            u32 d = smb + A_ST;
            bulk_g2s(d,         kh_g  + tbase, 8192, cx.mb[0]);
            bulk_g2s(d + 8192,  kl_g  + tbase, 8192, cx.mb[0]);
            bulk_g2s(d + 16384, vth_g + tbase, 8192, cx.mb[0]);
            bulk_g2s(d + 24576, vtl_g + tbase, 8192, cx.mb[0]);
            if (cx.n_iter > 1) {
                const size_t t1 = tbase + 8192;
                u32 d1 = d + A_STG;
                mbar_expect(cx.mb[1], A_STG);
                bulk_g2s(d1,         kh_g  + t1, 8192, cx.mb[1]);
                bulk_g2s(d1 + 8192,  kl_g  + t1, 8192, cx.mb[1]);
                bulk_g2s(d1 + 16384, vth_g + t1, 8192, cx.mb[1]);
                bulk_g2s(d1 + 24576, vtl_g + t1, 8192, cx.mb[1]);
            }
        }
        waitpar(cx.mb[0], cx.ph[0]); cx.ph[0] ^= 1;

        u32 qfh[4][4], qfl[4][4];
        #pragma unroll
        for (int ks = 0; ks < 4; ks++) {
            u32 off = abyte(lrowA, ks * 2 + lqA);
            ldsm4(qfh[ks], smb + A_QH + off);
            ldsm4(qfl[ks], smb + A_QL + off);
        }

        float o[8][4];
        #pragma unroll
        for (int nt = 0; nt < 8; nt++)
            #pragma unroll
            for (int i = 0; i < 4; i++) o[nt][i] = 0.f;
        cx.m0 = -1e30f; cx.m1 = -1e30f; cx.l0 = 0.f; cx.l1 = 0.f;

        float sA[8][4], sB[8][4];
        compute_S(cx, sA, qfh, qfl, 0, lane);

        for (int gi = 0; gi < cx.n_iter; gi += 2) {
            stage_body(cx, sA, sB, o, qfh, qfl, gi, lane, tid,
                       kh_g, kl_g, vth_g, vtl_g, tbase);
            if (gi + 1 < cx.n_iter)
                stage_body(cx, sB, sA, o, qfh, qfl, gi + 1, lane, tid,
                           kh_g, kl_g, vth_g, vtl_g, tbase);
        }

        // ---- epilogue ----
        float i0 = 1.0f / cx.l0, i1 = 1.0f / cx.l1;
        int gr = b * TT + tq * 64 + warp * 16 + (lane >> 2);
        #pragma unroll
        for (int nt = 0; nt < 8; nt++) {
            int h = nt * 8 + 2 * (lane & 3);
            float2 w0 = make_float2(o[nt][0] * i0, o[nt][1] * i0);
            float2 w1 = make_float2(o[nt][2] * i1, o[nt][3] * i1);
            *(float2*)&out[(size_t)gr * HD + h]       = w0;
            *(float2*)&out[(size_t)(gr + 8) * HD + h] = w1;
        }
    }
}

extern "C" void kernel_launch(void* const* d_in, const int* in_sizes, int n_in,
                              void* d_out, int out_size)
{
    const float* x  = (const float*)d_in[0];
    const float* Wk = (const float*)d_in[1];
    const float* Wq = (const float*)d_in[2];
    const float* Wv = (const float*)d_in[3];
    float* out = (float*)d_out;

    cudaFuncSetAttribute(proj_kernel, cudaFuncAttributeMaxDynamicSharedMemorySize, P_SMEM);
    cudaFuncSetAttribute(attn2_kernel, cudaFuncAttributeMaxDynamicSharedMemorySize, A_SMEM);

    wconv_kernel<<<dim3(192, 4), 256>>>(Wk, Wq, Wv);
    proj_kernel<<<BT / 64, 256, P_SMEM>>>(x);
    attn2_kernel<<<dim3(32, NB), 128, A_SMEM>>>(out);
}

// round 9
// speedup vs baseline: 1.0958x; 1.0958x over previous
#include <cuda_runtime.h>
#include <cuda_bf16.h>
#include <math.h>

#define HD 64
#define NE 1024
#define TT 4096
#define NB 4
#define BT (NB*TT)

typedef unsigned long long u64;
typedef unsigned int u32;

// ---- device scratch (no allocs allowed) ----
// W^T bf16 hi/lo, chunk-major + SW128-pre-swizzled: [chunk 16][n' 192][k 64]
__device__ __align__(128) __nv_bfloat16 g_wth[16*192*64];
__device__ __align__(128) __nv_bfloat16 g_wtl[16*192*64];
// q/k blocked: [tile 256][s 64][h 64] bf16, swizzled; v transposed: [tile][h 64][s 64]
__device__ __align__(128) __nv_bfloat16 g_qh[BT*HD];
__device__ __align__(128) __nv_bfloat16 g_ql[BT*HD];
__device__ __align__(128) __nv_bfloat16 g_kh[BT*HD];
__device__ __align__(128) __nv_bfloat16 g_kl[BT*HD];
__device__ __align__(128) __nv_bfloat16 g_vth[BT*HD];
__device__ __align__(128) __nv_bfloat16 g_vtl[BT*HD];

// ---------------- PTX helpers ----------------
__device__ __forceinline__ u32 s2u(const void* p) {
    return (u32)__cvta_generic_to_shared(p);
}
__device__ __forceinline__ void mbar_init(u32 mb, u32 cnt) {
    asm volatile("mbarrier.init.shared.b64 [%0], %1;" :: "r"(mb), "r"(cnt) : "memory");
}
__device__ __forceinline__ void mbar_expect(u32 mb, u32 tx) {
    asm volatile("mbarrier.arrive.expect_tx.shared.b64 _, [%0], %1;" :: "r"(mb), "r"(tx) : "memory");
}
__device__ __forceinline__ void bulk_g2s(u32 dst, const void* src, u32 bytes, u32 mb) {
    asm volatile("cp.async.bulk.shared::cluster.global.mbarrier::complete_tx::bytes [%0], [%1], %2, [%3];"
                 :: "r"(dst), "l"(src), "r"(bytes), "r"(mb) : "memory");
}
__device__ __forceinline__ void waitpar(u32 mb, u32 ph) {
    asm volatile(
        "{\n\t.reg .pred P;\n"
        "W%=:\n\t"
        "mbarrier.try_wait.parity.acquire.cta.shared::cta.b64 P, [%0], %1, 0x989680;\n\t"
        "@P bra D%=;\n\t"
        "bra W%=;\n"
        "D%=:\n\t}"
        :: "r"(mb), "r"(ph) : "memory");
}
// bf16x2 pack: low half = lo param, high half = hi param
__device__ __forceinline__ u32 bf2(float lo, float hi) {
    u32 d; asm("cvt.rn.bf16x2.f32 %0, %1, %2;" : "=r"(d) : "f"(hi), "f"(lo));
    return d;
}
__device__ __forceinline__ float lo16f(u32 h) { return __uint_as_float(h << 16); }
__device__ __forceinline__ float hi16f(u32 h) { return __uint_as_float(h & 0xFFFF0000u); }
__device__ __forceinline__ void ldsm4(u32* r, u32 addr) {
    asm volatile("ldmatrix.sync.aligned.m8n8.x4.shared.b16 {%0,%1,%2,%3}, [%4];"
        : "=r"(r[0]), "=r"(r[1]), "=r"(r[2]), "=r"(r[3]) : "r"(addr));
}
__device__ __forceinline__ void ldsm2(u32* r, u32 addr) {
    asm volatile("ldmatrix.sync.aligned.m8n8.x2.shared.b16 {%0,%1}, [%2];"
        : "=r"(r[0]), "=r"(r[1]) : "r"(addr));
}
__device__ __forceinline__ void mma_bf16(float* c, const u32* a, const u32* b) {
    asm volatile("mma.sync.aligned.m16n8k16.row.col.f32.bf16.bf16.f32 "
        "{%0,%1,%2,%3}, {%4,%5,%6,%7}, {%8,%9}, {%0,%1,%2,%3};"
        : "+f"(c[0]), "+f"(c[1]), "+f"(c[2]), "+f"(c[3])
        : "r"(a[0]), "r"(a[1]), "r"(a[2]), "r"(a[3]), "r"(b[0]), "r"(b[1]));
}
__device__ __forceinline__ u32 abyte(int row, int q) {
    return (u32)(row * 128 + (((q) ^ (row & 7)) << 4));
}

// ---------------------------------------------------------------------------
// Kernel 0: W transpose + bf16 hi/lo + chunk-major SW128 pre-swizzle.
// ---------------------------------------------------------------------------
__global__ void wconv_kernel(const float* __restrict__ Wk,
                             const float* __restrict__ Wq,
                             const float* __restrict__ Wv)
{
    int np  = blockIdx.x;            // 0..191
    int mat = np >> 6;
    int n   = np & 63;
    const float* W = (mat == 0) ? Wk : (mat == 1) ? Wq : Wv;
    char* dh = (char*)g_wth;
    char* dl = (char*)g_wtl;
    for (int k = threadIdx.x; k < NE; k += blockDim.x) {
        float v = W[k * HD + n];
        __nv_bfloat16 h = __float2bfloat16(v);
        float hf = __bfloat162float(h);
        __nv_bfloat16 l = __float2bfloat16(v - hf);
        int ch = k >> 6, kc = k & 63;
        u32 off = (u32)np * 128 + kc * 2;
        u32 sw  = off ^ ((np & 7) * 16);
        *(__nv_bfloat16*)(dh + ch * 24576 + sw) = h;
        *(__nv_bfloat16*)(dl + ch * 24576 + sw) = l;
    }
}

// ---------------------------------------------------------------------------
// Kernel 1: QKV projection via mma.sync bf16 hi/lo.
// CTA: 64 rows x 192 cols, 256 threads, 8 warps (4M x 2N), warp 16x96.
// W double-buffered via cp.async.bulk (proven R6 pipeline); x LDG->cvt->STS
// software-pipelined. smem 114816B -> 2 CTAs/SM, grid 256 covers all SMs.
// ---------------------------------------------------------------------------
#define NCH 16
#define Q_XH 128
#define Q_XL (128 + 8192)
#define Q_W  (128 + 16384)
#define WSTRIDE 49152
#define P_SMEM (Q_W + 2*WSTRIDE)     // 114816

__global__ __launch_bounds__(256, 2) void proj_kernel(const float* __restrict__ x)
{
    extern __shared__ char sm[];
    const u32 smb = s2u(sm);
    const int tid  = threadIdx.x;
    const int warp = tid >> 5;
    const int lane = tid & 31;
    const int wm   = warp >> 1;      // 0..3 : 16-row group
    const int wn   = warp & 1;       // 0..1 : 96-col group
    const int row0 = blockIdx.x * 64;

    const u32 mb0 = smb;
    const u32 mb1 = smb + 8;

    if (tid == 0) { mbar_init(mb0, 1); mbar_init(mb1, 1); }
    __syncthreads();

    const char* wh_g = (const char*)g_wth;
    const char* wl_g = (const char*)g_wtl;

    if (tid == 0) {
        mbar_expect(mb0, 49152);
        bulk_g2s(smb + Q_W,         wh_g, 24576, mb0);
        bulk_g2s(smb + Q_W + 24576, wl_g, 24576, mb0);
        mbar_expect(mb1, 49152);
        bulk_g2s(smb + Q_W + WSTRIDE,         wh_g + 24576, 24576, mb1);
        bulk_g2s(smb + Q_W + WSTRIDE + 24576, wl_g + 24576, 24576, mb1);
    }

    float C[12][4];
    #pragma unroll
    for (int nt = 0; nt < 12; nt++)
        #pragma unroll
        for (int i = 0; i < 4; i++) C[nt][i] = 0.f;

    // stage x chunk 0: 64 rows x 64 k
    float4 xr[4];
    #pragma unroll
    for (int i = 0; i < 4; i++) {
        int idx = tid + i * 256;            // 0..1023
        int r = idx >> 4, c4 = idx & 15;
        xr[i] = *(const float4*)&x[(size_t)(row0 + r) * NE + c4 * 4];
    }
    #pragma unroll
    for (int i = 0; i < 4; i++) {
        int idx = tid + i * 256;
        int r = idx >> 4, c4 = idx & 15;
        float4 v = xr[i];
        u32 h01 = bf2(v.x, v.y);
        u32 h23 = bf2(v.z, v.w);
        u32 l01 = bf2(v.x - lo16f(h01), v.y - hi16f(h01));
        u32 l23 = bf2(v.z - lo16f(h23), v.w - hi16f(h23));
        u32 off = (u32)r * 128 + c4 * 8;
        u32 sw  = off ^ ((r & 7) * 16);
        *(u64*)(sm + Q_XH + sw) = (u64)h01 | ((u64)h23 << 32);
        *(u64*)(sm + Q_XL + sw) = (u64)l01 | ((u64)l23 << 32);
    }
    __syncthreads();

    u32 ph[2] = {0, 0};
    const int rowA0 = wm * 16 + (lane & 15);
    const int qselA = lane >> 4;
    const int nrow0 = wn * 96 + (lane & 7);
    const int gB    = (lane >> 3) & 1;

    for (int c = 0; c < NCH; c++) {
        if (c < NCH - 1) {
            const int kk = (c + 1) * 64;
            #pragma unroll
            for (int i = 0; i < 4; i++) {
                int idx = tid + i * 256;
                int r = idx >> 4, c4 = idx & 15;
                xr[i] = *(const float4*)&x[(size_t)(row0 + r) * NE + kk + c4 * 4];
            }
        }

        waitpar((c & 1) ? mb1 : mb0, ph[c & 1]);
        ph[c & 1] ^= 1;

        const u32 wbase = smb + Q_W + (c & 1) * WSTRIDE;

        #pragma unroll
        for (int ks = 0; ks < 4; ks++) {
            u32 ah[4], al[4];
            u32 ba = abyte(rowA0, ks * 2 + qselA);
            ldsm4(ah, smb + Q_XH + ba);
            ldsm4(al, smb + Q_XL + ba);
            #pragma unroll
            for (int nt = 0; nt < 12; nt++) {
                u32 bh[2], bl[2];
                u32 bb = abyte(nrow0 + nt * 8, ks * 2 + gB);
                ldsm2(bh, wbase + bb);
                ldsm2(bl, wbase + 24576 + bb);
                mma_bf16(C[nt], ah, bh);
                mma_bf16(C[nt], ah, bl);
                mma_bf16(C[nt], al, bh);
            }
        }
        __syncthreads();   // x buffer + W buffer (c&1) consumed by all warps

        if (c < NCH - 1) {
            // store staged x chunk c+1
            #pragma unroll
            for (int i = 0; i < 4; i++) {
                int idx = tid + i * 256;
                int r = idx >> 4, c4 = idx & 15;
                float4 v = xr[i];
                u32 h01 = bf2(v.x, v.y);
                u32 h23 = bf2(v.z, v.w);
                u32 l01 = bf2(v.x - lo16f(h01), v.y - hi16f(h01));
                u32 l23 = bf2(v.z - lo16f(h23), v.w - hi16f(h23));
                u32 off = (u32)r * 128 + c4 * 8;
                u32 sw  = off ^ ((r & 7) * 16);
                *(u64*)(sm + Q_XH + sw) = (u64)h01 | ((u64)h23 << 32);
                *(u64*)(sm + Q_XL + sw) = (u64)l01 | ((u64)l23 << 32);
            }
            // kick W bulk for chunk c+2 into the buffer just freed
            if (tid == 0 && c + 2 < NCH) {
                u32 mb = (c & 1) ? mb1 : mb0;
                u32 dst = smb + Q_W + (c & 1) * WSTRIDE;
                mbar_expect(mb, 49152);
                bulk_g2s(dst,         wh_g + (size_t)(c + 2) * 24576, 24576, mb);
                bulk_g2s(dst + 24576, wl_g + (size_t)(c + 2) * 24576, 24576, mb);
            }
            __syncthreads();
        }
    }

    // ---- epilogue: q/k blocked [tile][s][h], v^T [tile][h][s], hi/lo bf16 ----
    {
        int r_lo = row0 + wm * 16 + (lane >> 2);   // and r_lo+8, same 64-tile
        size_t tb = (size_t)(r_lo >> 6) * 8192;
        int s0 = r_lo & 63, s1 = s0 + 8;
        #pragma unroll
        for (int nt = 0; nt < 12; nt++) {
            int col = wn * 96 + nt * 8 + 2 * (lane & 3);
            int mat = col >> 6;
            int h   = col & 63;
            float sc = (mat == 1) ? 0.03125f : 1.0f;   // 1024^-0.5 folded into q
            float v0 = C[nt][0] * sc, v1 = C[nt][1] * sc;
            float v2 = C[nt][2] * sc, v3 = C[nt][3] * sc;
            if (mat != 2) {
                char* dh = (mat == 0) ? (char*)g_kh : (char*)g_qh;
                char* dl = (mat == 0) ? (char*)g_kl : (char*)g_ql;
                u32 h01 = bf2(v0, v1);
                u32 l01 = bf2(v0 - lo16f(h01), v1 - hi16f(h01));
                u32 h23 = bf2(v2, v3);
                u32 l23 = bf2(v2 - lo16f(h23), v3 - hi16f(h23));
                size_t a0 = tb + s0 * 128 + ((((h >> 3) ^ (s0 & 7)) << 4) + (h & 7) * 2);
                size_t a1 = tb + s1 * 128 + ((((h >> 3) ^ (s1 & 7)) << 4) + (h & 7) * 2);
                *(u32*)(dh + a0) = h01;  *(u32*)(dl + a0) = l01;
                *(u32*)(dh + a1) = h23;  *(u32*)(dl + a1) = l23;
            } else {
                char* dh = (char*)g_vth;
                char* dl = (char*)g_vtl;
                float vv[4] = {v0, v1, v2, v3};
                #pragma unroll
                for (int e = 0; e < 4; e++) {
                    int hh = h + (e & 1);
                    int ss = (e < 2) ? s0 : s1;
                    __nv_bfloat16 bh = __float2bfloat16(vv[e]);
                    __nv_bfloat16 bl = __float2bfloat16(vv[e] - __bfloat162float(bh));
                    size_t a = tb + hh * 128 + ((((ss >> 3) ^ (hh & 7)) << 4) + (ss & 7) * 2);
                    *(__nv_bfloat16*)(dh + a) = bh;
                    *(__nv_bfloat16*)(dl + a) = bl;
                }
            }
        }
    }
}

// ---------------------------------------------------------------------------
// Kernel 2: causal flash attention via mma.sync bf16 hi/lo (exact R6 version).
// CTA = 128 threads (4 warps), q-tile M=64 (warp owns 16 rows), BK=64 stages
// double-buffered via cp.async.bulk. CTA processes tile pair (tq, 63-tq):
// uniform 65 stages. S C-frags reused in-register as PV A-frags.
// ---------------------------------------------------------------------------
#define A_QH  128
#define A_QL  (128 + 8192)
#define A_ST  (128 + 16384)
#define A_STG 32768
#define A_SMEM (A_ST + 2*A_STG)      // 82048

__global__ __launch_bounds__(128) void attn2_kernel(float* __restrict__ out)
{
    extern __shared__ char sm[];
    const u32 smb = s2u(sm);
    const int tid  = threadIdx.x;
    const int warp = tid >> 5;
    const int lane = tid & 31;
    const int b    = blockIdx.y;
    const int pidx = blockIdx.x;      // 0..31

    const u32 mb0 = smb, mb1 = smb + 8;
    if (tid == 0) { mbar_init(mb0, 1); mbar_init(mb1, 1); }
    __syncthreads();

    u32 ph[2] = {0, 0};

    // ldmatrix geometry
    const int lrowA = warp * 16 + (lane & 15);      // A-frag (Q) row
    const int lqA   = lane >> 4;                     // A-frag 16B-unit select
    const int browB = ((lane >> 4) << 3) + (lane & 7); // B-frag row-in-16
    const int bgB   = (lane >> 3) & 1;

    const char* qh_g  = (const char*)g_qh;
    const char* ql_g  = (const char*)g_ql;
    const char* kh_g  = (const char*)g_kh;
    const char* kl_g  = (const char*)g_kl;
    const char* vth_g = (const char*)g_vth;
    const char* vtl_g = (const char*)g_vtl;

    for (int ti = 0; ti < 2; ti++) {
        const int tq     = ti ? (63 - pidx) : pidx;
        const int n_iter = tq + 1;
        const size_t tgq = (size_t)(b * 64 + tq) * 8192;

        __syncthreads();   // previous tile's buffer consumers done
        if (tid == 0) {
            const size_t t0 = (size_t)(b * 64) * 8192;
            mbar_expect(mb0, 16384 + A_STG);
            bulk_g2s(smb + A_QH, qh_g + tgq, 8192, mb0);
            bulk_g2s(smb + A_QL, ql_g + tgq, 8192, mb0);
            u32 d = smb + A_ST;
            bulk_g2s(d,         kh_g  + t0, 8192, mb0);
            bulk_g2s(d + 8192,  kl_g  + t0, 8192, mb0);
            bulk_g2s(d + 16384, vth_g + t0, 8192, mb0);
            bulk_g2s(d + 24576, vtl_g + t0, 8192, mb0);
            if (n_iter > 1) {
                const size_t t1 = t0 + 8192;
                u32 d1 = d + A_STG;
                mbar_expect(mb1, A_STG);
                bulk_g2s(d1,         kh_g  + t1, 8192, mb1);
                bulk_g2s(d1 + 8192,  kl_g  + t1, 8192, mb1);
                bulk_g2s(d1 + 16384, vth_g + t1, 8192, mb1);
                bulk_g2s(d1 + 24576, vtl_g + t1, 8192, mb1);
            }
        }
        waitpar(mb0, ph[0]); ph[0] ^= 1;

        // Q frags (persistent in registers)
        u32 qfh[4][4], qfl[4][4];
        #pragma unroll
        for (int ks = 0; ks < 4; ks++) {
            u32 off = abyte(lrowA, ks * 2 + lqA);
            ldsm4(qfh[ks], smb + A_QH + off);
            ldsm4(qfl[ks], smb + A_QL + off);
        }

        float o[8][4];
        #pragma unroll
        for (int nt = 0; nt < 8; nt++)
            #pragma unroll
            for (int i = 0; i < 4; i++) o[nt][i] = 0.f;
        float m0 = -1e30f, m1 = -1e30f, l0 = 0.f, l1 = 0.f;

        for (int gi = 0; gi < n_iter; gi++) {
            const int s = gi & 1;
            if (gi > 0) { waitpar(s ? mb1 : mb0, ph[s]); ph[s] ^= 1; }
            const u32 kb = smb + A_ST + s * A_STG;
            const u32 vb = kb + 16384;

            // ---- S = Q K^T ----
            float sacc[8][4];
            #pragma unroll
            for (int nt = 0; nt < 8; nt++)
                #pragma unroll
                for (int i = 0; i < 4; i++) sacc[nt][i] = 0.f;

            #pragma unroll
            for (int ks = 0; ks < 4; ks++) {
                #pragma unroll
                for (int ntp = 0; ntp < 4; ntp++) {
                    int nr = ntp * 16 + browB;
                    u32 off = (u32)(nr * 128 + (((ks * 2 + bgB) ^ (nr & 7)) << 4));
                    u32 kh4[4], kl4[4];
                    ldsm4(kh4, kb + off);
                    ldsm4(kl4, kb + 8192 + off);
                    mma_bf16(sacc[2*ntp],   qfh[ks], kh4);
                    mma_bf16(sacc[2*ntp],   qfh[ks], kl4);
                    mma_bf16(sacc[2*ntp],   qfl[ks], kh4);
                    mma_bf16(sacc[2*ntp+1], qfh[ks], kh4 + 2);
                    mma_bf16(sacc[2*ntp+1], qfh[ks], kl4 + 2);
                    mma_bf16(sacc[2*ntp+1], qfl[ks], kh4 + 2);
                }
            }

            // ---- causal mask (diagonal stage only) ----
            if (gi == tq) {
                int rl = warp * 16 + (lane >> 2);
                #pragma unroll
                for (int nt = 0; nt < 8; nt++) {
                    int cl = nt * 8 + 2 * (lane & 3);
                    if (cl     > rl)     sacc[nt][0] = -1e30f;
                    if (cl + 1 > rl)     sacc[nt][1] = -1e30f;
                    if (cl     > rl + 8) sacc[nt][2] = -1e30f;
                    if (cl + 1 > rl + 8) sacc[nt][3] = -1e30f;
                }
            }

            // ---- online softmax (rows: lane>>2 and +8; 4 lanes share a row) ----
            float mx0 = sacc[0][0], mx1 = sacc[0][2];
            #pragma unroll
            for (int nt = 0; nt < 8; nt++) {
                mx0 = fmaxf(mx0, fmaxf(sacc[nt][0], sacc[nt][1]));
                mx1 = fmaxf(mx1, fmaxf(sacc[nt][2], sacc[nt][3]));
            }
            mx0 = fmaxf(mx0, __shfl_xor_sync(0xffffffffu, mx0, 1));
            mx0 = fmaxf(mx0, __shfl_xor_sync(0xffffffffu, mx0, 2));
            mx1 = fmaxf(mx1, __shfl_xor_sync(0xffffffffu, mx1, 1));
            mx1 = fmaxf(mx1, __shfl_xor_sync(0xffffffffu, mx1, 2));
            float mn0 = fmaxf(m0, mx0), mn1 = fmaxf(m1, mx1);
            float sc0 = __expf(m0 - mn0), sc1 = __expf(m1 - mn1);
            float sum0 = 0.f, sum1 = 0.f;
            #pragma unroll
            for (int nt = 0; nt < 8; nt++) {
                sacc[nt][0] = __expf(sacc[nt][0] - mn0);
                sacc[nt][1] = __expf(sacc[nt][1] - mn0);
                sacc[nt][2] = __expf(sacc[nt][2] - mn1);
                sacc[nt][3] = __expf(sacc[nt][3] - mn1);
                sum0 += sacc[nt][0] + sacc[nt][1];
                sum1 += sacc[nt][2] + sacc[nt][3];
            }
            sum0 += __shfl_xor_sync(0xffffffffu, sum0, 1);
            sum0 += __shfl_xor_sync(0xffffffffu, sum0, 2);
            sum1 += __shfl_xor_sync(0xffffffffu, sum1, 1);
            sum1 += __shfl_xor_sync(0xffffffffu, sum1, 2);
            l0 = l0 * sc0 + sum0;  l1 = l1 * sc1 + sum1;
            m0 = mn0;  m1 = mn1;
            #pragma unroll
            for (int nt = 0; nt < 8; nt++) {
                o[nt][0] *= sc0;  o[nt][1] *= sc0;
                o[nt][2] *= sc1;  o[nt][3] *= sc1;
            }

            // ---- O += P V  (P C-frags -> A-frags in-register, hi/lo) ----
            #pragma unroll
            for (int kt = 0; kt < 4; kt++) {
                const float* sA = sacc[2*kt];
                const float* sB = sacc[2*kt+1];
                u32 pH[4], pL[4];
                pH[0] = bf2(sA[0], sA[1]);
                pH[1] = bf2(sA[2], sA[3]);
                pH[2] = bf2(sB[0], sB[1]);
                pH[3] = bf2(sB[2], sB[3]);
                pL[0] = bf2(sA[0] - lo16f(pH[0]), sA[1] - hi16f(pH[0]));
                pL[1] = bf2(sA[2] - lo16f(pH[1]), sA[3] - hi16f(pH[1]));
                pL[2] = bf2(sB[0] - lo16f(pH[2]), sB[1] - hi16f(pH[2]));
                pL[3] = bf2(sB[2] - lo16f(pH[3]), sB[3] - hi16f(pH[3]));
                #pragma unroll
                for (int ntp = 0; ntp < 4; ntp++) {
                    int nr = ntp * 16 + browB;
                    u32 off = (u32)(nr * 128 + (((kt * 2 + bgB) ^ (nr & 7)) << 4));
                    u32 vh4[4], vl4[4];
                    ldsm4(vh4, vb + off);
                    ldsm4(vl4, vb + 8192 + off);
                    mma_bf16(o[2*ntp],   pH, vh4);
                    mma_bf16(o[2*ntp],   pH, vl4);
                    mma_bf16(o[2*ntp],   pL, vh4);
                    mma_bf16(o[2*ntp+1], pH, vh4 + 2);
                    mma_bf16(o[2*ntp+1], pH, vl4 + 2);
                    mma_bf16(o[2*ntp+1], pL, vh4 + 2);
                }
            }

            __syncthreads();
            if (tid == 0 && gi + 2 < n_iter) {
                const size_t tn = (size_t)(b * 64 + gi + 2) * 8192;
                u32 mb = s ? mb1 : mb0;
                u32 d  = smb + A_ST + s * A_STG;
                mbar_expect(mb, A_STG);
                bulk_g2s(d,         kh_g  + tn, 8192, mb);
                bulk_g2s(d + 8192,  kl_g  + tn, 8192, mb);
                bulk_g2s(d + 16384, vth_g + tn, 8192, mb);
                bulk_g2s(d + 24576, vtl_g + tn, 8192, mb);
            }
        }

        // ---- epilogue ----
        float i0 = 1.0f / l0, i1 = 1.0f / l1;
        int gr = b * TT + tq * 64 + warp * 16 + (lane >> 2);
        #pragma unroll
        for (int nt = 0; nt < 8; nt++) {
            int h = nt * 8 + 2 * (lane & 3);
            float2 w0 = make_float2(o[nt][0] * i0, o[nt][1] * i0);
            float2 w1 = make_float2(o[nt][2] * i1, o[nt][3] * i1);
            *(float2*)&out[(size_t)gr * HD + h]       = w0;
            *(float2*)&out[(size_t)(gr + 8) * HD + h] = w1;
        }
    }
}

extern "C" void kernel_launch(void* const* d_in, const int* in_sizes, int n_in,
                              void* d_out, int out_size)
{
    const float* x  = (const float*)d_in[0];
    const float* Wk = (const float*)d_in[1];
    const float* Wq = (const float*)d_in[2];
    const float* Wv = (const float*)d_in[3];
    float* out = (float*)d_out;

    cudaFuncSetAttribute(proj_kernel, cudaFuncAttributeMaxDynamicSharedMemorySize, P_SMEM);
    cudaFuncSetAttribute(attn2_kernel, cudaFuncAttributeMaxDynamicSharedMemorySize, A_SMEM);

    wconv_kernel<<<192, 256>>>(Wk, Wq, Wv);
    proj_kernel<<<BT / 64, 256, P_SMEM>>>(x);
    attn2_kernel<<<dim3(32, NB), 128, A_SMEM>>>(out);
}

// round 10
// speedup vs baseline: 1.7188x; 1.5686x over previous
#include <cuda_runtime.h>
#include <cuda_bf16.h>
#include <math.h>

#define HD 64
#define NE 1024
#define TT 4096
#define NB 4
#define BT (NB*TT)

typedef unsigned long long u64;
typedef unsigned int u32;

// ---- device scratch (no allocs allowed) ----
// W^T bf16 hi/lo, chunk-major + SW128-pre-swizzled: [chunk 16][n' 192][k 64]
__device__ __align__(128) __nv_bfloat16 g_wth[16*192*64];
__device__ __align__(128) __nv_bfloat16 g_wtl[16*192*64];
// q/k blocked: [tile 256][s 64][h 64] bf16, swizzled; v transposed: [tile][h 64][s 64]
__device__ __align__(128) __nv_bfloat16 g_qh[BT*HD];
__device__ __align__(128) __nv_bfloat16 g_ql[BT*HD];
__device__ __align__(128) __nv_bfloat16 g_kh[BT*HD];
__device__ __align__(128) __nv_bfloat16 g_kl[BT*HD];
__device__ __align__(128) __nv_bfloat16 g_vth[BT*HD];
__device__ __align__(128) __nv_bfloat16 g_vtl[BT*HD];
// split-KV partials: 4 batches x 32 big tiles x 2 halves = 256 units
__device__ __align__(128) float g_po[256*64*64];
__device__ float g_pm[256*64];
__device__ float g_pl[256*64];

// ---------------- PTX helpers ----------------
__device__ __forceinline__ u32 s2u(const void* p) {
    return (u32)__cvta_generic_to_shared(p);
}
__device__ __forceinline__ void mbar_init(u32 mb, u32 cnt) {
    asm volatile("mbarrier.init.shared.b64 [%0], %1;" :: "r"(mb), "r"(cnt) : "memory");
}
__device__ __forceinline__ void mbar_expect(u32 mb, u32 tx) {
    asm volatile("mbarrier.arrive.expect_tx.shared.b64 _, [%0], %1;" :: "r"(mb), "r"(tx) : "memory");
}
__device__ __forceinline__ void bulk_g2s(u32 dst, const void* src, u32 bytes, u32 mb) {
    asm volatile("cp.async.bulk.shared::cluster.global.mbarrier::complete_tx::bytes [%0], [%1], %2, [%3];"
                 :: "r"(dst), "l"(src), "r"(bytes), "r"(mb) : "memory");
}
__device__ __forceinline__ void waitpar(u32 mb, u32 ph) {
    asm volatile(
        "{\n\t.reg .pred P;\n"
        "W%=:\n\t"
        "mbarrier.try_wait.parity.acquire.cta.shared::cta.b64 P, [%0], %1, 0x989680;\n\t"
        "@P bra D%=;\n\t"
        "bra W%=;\n"
        "D%=:\n\t}"
        :: "r"(mb), "r"(ph) : "memory");
}
// bf16x2 pack: low half = lo param, high half = hi param
__device__ __forceinline__ u32 bf2(float lo, float hi) {
    u32 d; asm("cvt.rn.bf16x2.f32 %0, %1, %2;" : "=r"(d) : "f"(hi), "f"(lo));
    return d;
}
__device__ __forceinline__ float lo16f(u32 h) { return __uint_as_float(h << 16); }
__device__ __forceinline__ float hi16f(u32 h) { return __uint_as_float(h & 0xFFFF0000u); }
__device__ __forceinline__ void ldsm4(u32* r, u32 addr) {
    asm volatile("ldmatrix.sync.aligned.m8n8.x4.shared.b16 {%0,%1,%2,%3}, [%4];"
        : "=r"(r[0]), "=r"(r[1]), "=r"(r[2]), "=r"(r[3]) : "r"(addr));
}
__device__ __forceinline__ void ldsm2(u32* r, u32 addr) {
    asm volatile("ldmatrix.sync.aligned.m8n8.x2.shared.b16 {%0,%1}, [%2];"
        : "=r"(r[0]), "=r"(r[1]) : "r"(addr));
}
__device__ __forceinline__ void mma_bf16(float* c, const u32* a, const u32* b) {
    asm volatile("mma.sync.aligned.m16n8k16.row.col.f32.bf16.bf16.f32 "
        "{%0,%1,%2,%3}, {%4,%5,%6,%7}, {%8,%9}, {%0,%1,%2,%3};"
        : "+f"(c[0]), "+f"(c[1]), "+f"(c[2]), "+f"(c[3])
        : "r"(a[0]), "r"(a[1]), "r"(a[2]), "r"(a[3]), "r"(b[0]), "r"(b[1]));
}
__device__ __forceinline__ u32 abyte(int row, int q) {
    return (u32)(row * 128 + (((q) ^ (row & 7)) << 4));
}

// ---------------------------------------------------------------------------
// Kernel 0: W transpose + bf16 hi/lo + chunk-major SW128 pre-swizzle. (R6)
// ---------------------------------------------------------------------------
__global__ void wconv_kernel(const float* __restrict__ Wk,
                             const float* __restrict__ Wq,
                             const float* __restrict__ Wv)
{
    int np  = blockIdx.x;            // 0..191
    int mat = np >> 6;
    int n   = np & 63;
    const float* W = (mat == 0) ? Wk : (mat == 1) ? Wq : Wv;
    char* dh = (char*)g_wth;
    char* dl = (char*)g_wtl;
    for (int k = threadIdx.x; k < NE; k += blockDim.x) {
        float v = W[k * HD + n];
        __nv_bfloat16 h = __float2bfloat16(v);
        float hf = __bfloat162float(h);
        __nv_bfloat16 l = __float2bfloat16(v - hf);
        int ch = k >> 6, kc = k & 63;
        u32 off = (u32)np * 128 + kc * 2;
        u32 sw  = off ^ ((np & 7) * 16);
        *(__nv_bfloat16*)(dh + ch * 24576 + sw) = h;
        *(__nv_bfloat16*)(dl + ch * 24576 + sw) = l;
    }
}

// ---------------------------------------------------------------------------
// Kernel 1: QKV projection via mma.sync bf16 hi/lo. (exact R6 version, 150.7us run)
// CTA: 128 rows x 192 cols, 256 threads, 8 warps (4M x 2N), warp 32x96.
// ---------------------------------------------------------------------------
#define NCH 16
#define OFF_XH 128
#define OFF_XL (128 + 16384)
#define OFF_W  (128 + 32768)
#define WSTRIDE 49152
#define P_SMEM (OFF_W + 2*WSTRIDE)

__global__ __launch_bounds__(256, 1) void proj_kernel(const float* __restrict__ x)
{
    extern __shared__ char sm[];
    const u32 smb = s2u(sm);
    const int tid  = threadIdx.x;
    const int warp = tid >> 5;
    const int lane = tid & 31;
    const int wm   = warp >> 1;
    const int wn   = warp & 1;
    const int row0 = blockIdx.x * 128;

    const u32 mb0 = smb;
    const u32 mb1 = smb + 8;

    if (tid == 0) { mbar_init(mb0, 1); mbar_init(mb1, 1); }
    __syncthreads();

    const char* wh_g = (const char*)g_wth;
    const char* wl_g = (const char*)g_wtl;

    if (tid == 0) {
        mbar_expect(mb0, 49152);
        bulk_g2s(smb + OFF_W,         wh_g, 24576, mb0);
        bulk_g2s(smb + OFF_W + 24576, wl_g, 24576, mb0);
        mbar_expect(mb1, 49152);
        bulk_g2s(smb + OFF_W + WSTRIDE,         wh_g + 24576, 24576, mb1);
        bulk_g2s(smb + OFF_W + WSTRIDE + 24576, wl_g + 24576, 24576, mb1);
    }

    float C[2][12][4];
    #pragma unroll
    for (int mt = 0; mt < 2; mt++)
        #pragma unroll
        for (int nt = 0; nt < 12; nt++)
            #pragma unroll
            for (int i = 0; i < 4; i++) C[mt][nt][i] = 0.f;

    float4 xr[8];
    #pragma unroll
    for (int i = 0; i < 8; i++) {
        int idx = tid + i * 256;
        int r = idx >> 4, c4 = idx & 15;
        xr[i] = *(const float4*)&x[(size_t)(row0 + r) * NE + c4 * 4];
    }
    #pragma unroll
    for (int i = 0; i < 8; i++) {
        int idx = tid + i * 256;
        int r = idx >> 4, c4 = idx & 15;
        float4 v = xr[i];
        u32 h01 = bf2(v.x, v.y);
        u32 h23 = bf2(v.z, v.w);
        u32 l01 = bf2(v.x - lo16f(h01), v.y - hi16f(h01));
        u32 l23 = bf2(v.z - lo16f(h23), v.w - hi16f(h23));
        u32 off = (u32)r * 128 + c4 * 8;
        u32 sw  = off ^ ((r & 7) * 16);
        *(u64*)(sm + OFF_XH + sw) = (u64)h01 | ((u64)h23 << 32);
        *(u64*)(sm + OFF_XL + sw) = (u64)l01 | ((u64)l23 << 32);
    }
    __syncthreads();

    u32 ph[2] = {0, 0};
    const int rowA0 = wm * 32 + (lane & 15);
    const int qselA = lane >> 4;
    const int nrow0 = wn * 96 + (lane & 7);
    const int gB    = (lane >> 3) & 1;

    for (int c = 0; c < NCH; c++) {
        if (c < NCH - 1) {
            const int kk = (c + 1) * 64;
            #pragma unroll
            for (int i = 0; i < 8; i++) {
                int idx = tid + i * 256;
                int r = idx >> 4, c4 = idx & 15;
                xr[i] = *(const float4*)&x[(size_t)(row0 + r) * NE + kk + c4 * 4];
            }
        }

        waitpar((c & 1) ? mb1 : mb0, ph[c & 1]);
        ph[c & 1] ^= 1;

        const u32 wbase = smb + OFF_W + (c & 1) * WSTRIDE;

        #pragma unroll
        for (int ks = 0; ks < 4; ks++) {
            u32 ah[2][4], al[2][4];
            #pragma unroll
            for (int mt = 0; mt < 2; mt++) {
                u32 ba = abyte(rowA0 + mt * 16, ks * 2 + qselA);
                ldsm4(ah[mt], smb + OFF_XH + ba);
                ldsm4(al[mt], smb + OFF_XL + ba);
            }
            #pragma unroll
            for (int nt = 0; nt < 12; nt++) {
                u32 bh[2], bl[2];
                u32 bb = abyte(nrow0 + nt * 8, ks * 2 + gB);
                ldsm2(bh, wbase + bb);
                ldsm2(bl, wbase + 24576 + bb);
                #pragma unroll
                for (int mt = 0; mt < 2; mt++) {
                    mma_bf16(C[mt][nt], ah[mt], bh);
                    mma_bf16(C[mt][nt], ah[mt], bl);
                    mma_bf16(C[mt][nt], al[mt], bh);
                }
            }
        }
        __syncthreads();

        if (c < NCH - 1) {
            #pragma unroll
            for (int i = 0; i < 8; i++) {
                int idx = tid + i * 256;
                int r = idx >> 4, c4 = idx & 15;
                float4 v = xr[i];
                u32 h01 = bf2(v.x, v.y);
                u32 h23 = bf2(v.z, v.w);
                u32 l01 = bf2(v.x - lo16f(h01), v.y - hi16f(h01));
                u32 l23 = bf2(v.z - lo16f(h23), v.w - hi16f(h23));
                u32 off = (u32)r * 128 + c4 * 8;
                u32 sw  = off ^ ((r & 7) * 16);
                *(u64*)(sm + OFF_XH + sw) = (u64)h01 | ((u64)h23 << 32);
                *(u64*)(sm + OFF_XL + sw) = (u64)l01 | ((u64)l23 << 32);
            }
            if (tid == 0 && c + 2 < NCH) {
                u32 mb = (c & 1) ? mb1 : mb0;
                u32 dst = smb + OFF_W + (c & 1) * WSTRIDE;
                mbar_expect(mb, 49152);
                bulk_g2s(dst,         wh_g + (size_t)(c + 2) * 24576, 24576, mb);
                bulk_g2s(dst + 24576, wl_g + (size_t)(c + 2) * 24576, 24576, mb);
            }
        }
        __syncthreads();
    }

    // ---- epilogue: q/k blocked [tile][s][h], v^T [tile][h][s], hi/lo bf16 ----
    #pragma unroll
    for (int mt = 0; mt < 2; mt++) {
        int r_lo = row0 + wm * 32 + mt * 16 + (lane >> 2);
        size_t tb = (size_t)(r_lo >> 6) * 8192;
        int s0 = r_lo & 63, s1 = s0 + 8;
        #pragma unroll
        for (int nt = 0; nt < 12; nt++) {
            int col = wn * 96 + nt * 8 + 2 * (lane & 3);
            int mat = col >> 6;
            int h   = col & 63;
            float sc = (mat == 1) ? 0.03125f : 1.0f;   // 1024^-0.5 folded into q
            float v0 = C[mt][nt][0] * sc, v1 = C[mt][nt][1] * sc;
            float v2 = C[mt][nt][2] * sc, v3 = C[mt][nt][3] * sc;
            if (mat != 2) {
                char* dh = (mat == 0) ? (char*)g_kh : (char*)g_qh;
                char* dl = (mat == 0) ? (char*)g_kl : (char*)g_ql;
                u32 h01 = bf2(v0, v1);
                u32 l01 = bf2(v0 - lo16f(h01), v1 - hi16f(h01));
                u32 h23 = bf2(v2, v3);
                u32 l23 = bf2(v2 - lo16f(h23), v3 - hi16f(h23));
                size_t a0 = tb + s0 * 128 + ((((h >> 3) ^ (s0 & 7)) << 4) + (h & 7) * 2);
                size_t a1 = tb + s1 * 128 + ((((h >> 3) ^ (s1 & 7)) << 4) + (h & 7) * 2);
                *(u32*)(dh + a0) = h01;  *(u32*)(dl + a0) = l01;
                *(u32*)(dh + a1) = h23;  *(u32*)(dl + a1) = l23;
            } else {
                char* dh = (char*)g_vth;
                char* dl = (char*)g_vtl;
                float vv[4] = {v0, v1, v2, v3};
                #pragma unroll
                for (int e = 0; e < 4; e++) {
                    int hh = h + (e & 1);
                    int ss = (e < 2) ? s0 : s1;
                    __nv_bfloat16 bh = __float2bfloat16(vv[e]);
                    __nv_bfloat16 bl = __float2bfloat16(vv[e] - __bfloat162float(bh));
                    size_t a = tb + hh * 128 + ((((ss >> 3) ^ (hh & 7)) << 4) + (ss & 7) * 2);
                    *(__nv_bfloat16*)(dh + a) = bh;
                    *(__nv_bfloat16*)(dl + a) = bl;
                }
            }
        }
    }
}

// ---------------------------------------------------------------------------
// Kernel 2: causal flash attention, split-KV scheduling. Inner loop = exact R6.
// Work unit u (0..95) per batch:
//   u < 64 : half of big tile  tq = 63-(u>>1), half = u&1   (split-KV)
//   u >= 64: whole small tile  tq = 95-u
// Split units write unnormalized (O,m,l) partials; merge kernel combines.
// 2 CTAs/SM co-resident (82KB smem), 384 CTAs, largest-first.
// ---------------------------------------------------------------------------
#define A_QH  128
#define A_QL  (128 + 8192)
#define A_ST  (128 + 16384)
#define A_STG 32768
#define A_SMEM (A_ST + 2*A_STG)      // 82048

__global__ __launch_bounds__(128) void attn3_kernel(float* __restrict__ out)
{
    extern __shared__ char sm[];
    const u32 smb = s2u(sm);
    const int tid  = threadIdx.x;
    const int warp = tid >> 5;
    const int lane = tid & 31;
    const int b    = blockIdx.y;
    const int u    = blockIdx.x;      // 0..95

    int tq, st0, st1, pid;
    if (u < 64) {
        tq = 63 - (u >> 1);
        const int half = u & 1;
        const int n  = tq + 1;
        const int h0 = (n + 1) >> 1;
        st0 = half ? h0 : 0;
        st1 = half ? n  : h0;
        pid = ((b * 32) + (tq - 32)) * 2 + half;
    } else {
        tq = 95 - u;
        st0 = 0; st1 = tq + 1;
        pid = -1;
    }
    const int cnt = st1 - st0;

    const u32 mb0 = smb, mb1 = smb + 8;
    if (tid == 0) { mbar_init(mb0, 1); mbar_init(mb1, 1); }
    __syncthreads();

    u32 ph[2] = {0, 0};

    const int lrowA = warp * 16 + (lane & 15);
    const int lqA   = lane >> 4;
    const int browB = ((lane >> 4) << 3) + (lane & 7);
    const int bgB   = (lane >> 3) & 1;

    const char* qh_g  = (const char*)g_qh;
    const char* ql_g  = (const char*)g_ql;
    const char* kh_g  = (const char*)g_kh;
    const char* kl_g  = (const char*)g_kl;
    const char* vth_g = (const char*)g_vth;
    const char* vtl_g = (const char*)g_vtl;

    const size_t tbase = (size_t)(b * 64) * 8192;
    const size_t tgq   = (size_t)(b * 64 + tq) * 8192;

    if (tid == 0) {
        const size_t t0 = tbase + (size_t)st0 * 8192;
        mbar_expect(mb0, 16384 + A_STG);
        bulk_g2s(smb + A_QH, qh_g + tgq, 8192, mb0);
        bulk_g2s(smb + A_QL, ql_g + tgq, 8192, mb0);
        u32 d = smb + A_ST;
        bulk_g2s(d,         kh_g  + t0, 8192, mb0);
        bulk_g2s(d + 8192,  kl_g  + t0, 8192, mb0);
        bulk_g2s(d + 16384, vth_g + t0, 8192, mb0);
        bulk_g2s(d + 24576, vtl_g + t0, 8192, mb0);
        if (cnt > 1) {
            const size_t t1 = t0 + 8192;
            u32 d1 = d + A_STG;
            mbar_expect(mb1, A_STG);
            bulk_g2s(d1,         kh_g  + t1, 8192, mb1);
            bulk_g2s(d1 + 8192,  kl_g  + t1, 8192, mb1);
            bulk_g2s(d1 + 16384, vth_g + t1, 8192, mb1);
            bulk_g2s(d1 + 24576, vtl_g + t1, 8192, mb1);
        }
    }
    waitpar(mb0, ph[0]); ph[0] ^= 1;

    // Q frags (persistent in registers)
    u32 qfh[4][4], qfl[4][4];
    #pragma unroll
    for (int ks = 0; ks < 4; ks++) {
        u32 off = abyte(lrowA, ks * 2 + lqA);
        ldsm4(qfh[ks], smb + A_QH + off);
        ldsm4(qfl[ks], smb + A_QL + off);
    }

    float o[8][4];
    #pragma unroll
    for (int nt = 0; nt < 8; nt++)
        #pragma unroll
        for (int i = 0; i < 4; i++) o[nt][i] = 0.f;
    float m0 = -1e30f, m1 = -1e30f, l0 = 0.f, l1 = 0.f;

    for (int i = 0; i < cnt; i++) {
        const int gi = st0 + i;
        const int s  = i & 1;
        if (i > 0) { waitpar(s ? mb1 : mb0, ph[s]); ph[s] ^= 1; }
        const u32 kb = smb + A_ST + s * A_STG;
        const u32 vb = kb + 16384;

        // ---- S = Q K^T ----
        float sacc[8][4];
        #pragma unroll
        for (int nt = 0; nt < 8; nt++)
            #pragma unroll
            for (int j = 0; j < 4; j++) sacc[nt][j] = 0.f;

        #pragma unroll
        for (int ks = 0; ks < 4; ks++) {
            #pragma unroll
            for (int ntp = 0; ntp < 4; ntp++) {
                int nr = ntp * 16 + browB;
                u32 off = (u32)(nr * 128 + (((ks * 2 + bgB) ^ (nr & 7)) << 4));
                u32 kh4[4], kl4[4];
                ldsm4(kh4, kb + off);
                ldsm4(kl4, kb + 8192 + off);
                mma_bf16(sacc[2*ntp],   qfh[ks], kh4);
                mma_bf16(sacc[2*ntp],   qfh[ks], kl4);
                mma_bf16(sacc[2*ntp],   qfl[ks], kh4);
                mma_bf16(sacc[2*ntp+1], qfh[ks], kh4 + 2);
                mma_bf16(sacc[2*ntp+1], qfh[ks], kl4 + 2);
                mma_bf16(sacc[2*ntp+1], qfl[ks], kh4 + 2);
            }
        }

        // ---- causal mask (diagonal stage only) ----
        if (gi == tq) {
            int rl = warp * 16 + (lane >> 2);
            #pragma unroll
            for (int nt = 0; nt < 8; nt++) {
                int cl = nt * 8 + 2 * (lane & 3);
                if (cl     > rl)     sacc[nt][0] = -1e30f;
                if (cl + 1 > rl)     sacc[nt][1] = -1e30f;
                if (cl     > rl + 8) sacc[nt][2] = -1e30f;
                if (cl + 1 > rl + 8) sacc[nt][3] = -1e30f;
            }
        }

        // ---- online softmax ----
        float mx0 = sacc[0][0], mx1 = sacc[0][2];
        #pragma unroll
        for (int nt = 0; nt < 8; nt++) {
            mx0 = fmaxf(mx0, fmaxf(sacc[nt][0], sacc[nt][1]));
            mx1 = fmaxf(mx1, fmaxf(sacc[nt][2], sacc[nt][3]));
        }
        mx0 = fmaxf(mx0, __shfl_xor_sync(0xffffffffu, mx0, 1));
        mx0 = fmaxf(mx0, __shfl_xor_sync(0xffffffffu, mx0, 2));
        mx1 = fmaxf(mx1, __shfl_xor_sync(0xffffffffu, mx1, 1));
        mx1 = fmaxf(mx1, __shfl_xor_sync(0xffffffffu, mx1, 2));
        float mn0 = fmaxf(m0, mx0), mn1 = fmaxf(m1, mx1);
        float sc0 = __expf(m0 - mn0), sc1 = __expf(m1 - mn1);
        float sum0 = 0.f, sum1 = 0.f;
        #pragma unroll
        for (int nt = 0; nt < 8; nt++) {
            sacc[nt][0] = __expf(sacc[nt][0] - mn0);
            sacc[nt][1] = __expf(sacc[nt][1] - mn0);
            sacc[nt][2] = __expf(sacc[nt][2] - mn1);
            sacc[nt][3] = __expf(sacc[nt][3] - mn1);
            sum0 += sacc[nt][0] + sacc[nt][1];
            sum1 += sacc[nt][2] + sacc[nt][3];
        }
        sum0 += __shfl_xor_sync(0xffffffffu, sum0, 1);
        sum0 += __shfl_xor_sync(0xffffffffu, sum0, 2);
        sum1 += __shfl_xor_sync(0xffffffffu, sum1, 1);
        sum1 += __shfl_xor_sync(0xffffffffu, sum1, 2);
        l0 = l0 * sc0 + sum0;  l1 = l1 * sc1 + sum1;
        m0 = mn0;  m1 = mn1;
        #pragma unroll
        for (int nt = 0; nt < 8; nt++) {
            o[nt][0] *= sc0;  o[nt][1] *= sc0;
            o[nt][2] *= sc1;  o[nt][3] *= sc1;
        }

        // ---- O += P V ----
        #pragma unroll
        for (int kt = 0; kt < 4; kt++) {
            const float* sA = sacc[2*kt];
            const float* sB = sacc[2*kt+1];
            u32 pH[4], pL[4];
            pH[0] = bf2(sA[0], sA[1]);
            pH[1] = bf2(sA[2], sA[3]);
            pH[2] = bf2(sB[0], sB[1]);
            pH[3] = bf2(sB[2], sB[3]);
            pL[0] = bf2(sA[0] - lo16f(pH[0]), sA[1] - hi16f(pH[0]));
            pL[1] = bf2(sA[2] - lo16f(pH[1]), sA[3] - hi16f(pH[1]));
            pL[2] = bf2(sB[0] - lo16f(pH[2]), sB[1] - hi16f(pH[2]));
            pL[3] = bf2(sB[2] - lo16f(pH[3]), sB[3] - hi16f(pH[3]));
            #pragma unroll
            for (int ntp = 0; ntp < 4; ntp++) {
                int nr = ntp * 16 + browB;
                u32 off = (u32)(nr * 128 + (((kt * 2 + bgB) ^ (nr & 7)) << 4));
                u32 vh4[4], vl4[4];
                ldsm4(vh4, vb + off);
                ldsm4(vl4, vb + 8192 + off);
                mma_bf16(o[2*ntp],   pH, vh4);
                mma_bf16(o[2*ntp],   pH, vl4);
                mma_bf16(o[2*ntp],   pL, vh4);
                mma_bf16(o[2*ntp+1], pH, vh4 + 2);
                mma_bf16(o[2*ntp+1], pH, vl4 + 2);
                mma_bf16(o[2*ntp+1], pL, vh4 + 2);
            }
        }

        __syncthreads();
        if (tid == 0 && i + 2 < cnt) {
            const size_t tn = tbase + (size_t)(gi + 2) * 8192;
            u32 mb = s ? mb1 : mb0;
            u32 d  = smb + A_ST + s * A_STG;
            mbar_expect(mb, A_STG);
            bulk_g2s(d,         kh_g  + tn, 8192, mb);
            bulk_g2s(d + 8192,  kl_g  + tn, 8192, mb);
            bulk_g2s(d + 16384, vth_g + tn, 8192, mb);
            bulk_g2s(d + 24576, vtl_g + tn, 8192, mb);
        }
    }

    // ---- epilogue ----
    const int rloc = warp * 16 + (lane >> 2);
    if (pid < 0) {
        float i0 = 1.0f / l0, i1 = 1.0f / l1;
        int gr = b * TT + tq * 64 + rloc;
        #pragma unroll
        for (int nt = 0; nt < 8; nt++) {
            int h = nt * 8 + 2 * (lane & 3);
            float2 w0 = make_float2(o[nt][0] * i0, o[nt][1] * i0);
            float2 w1 = make_float2(o[nt][2] * i1, o[nt][3] * i1);
            *(float2*)&out[(size_t)gr * HD + h]       = w0;
            *(float2*)&out[(size_t)(gr + 8) * HD + h] = w1;
        }
    } else {
        float* po = g_po + (size_t)pid * 4096;
        #pragma unroll
        for (int nt = 0; nt < 8; nt++) {
            int h = nt * 8 + 2 * (lane & 3);
            *(float2*)&po[rloc * 64 + h]       = make_float2(o[nt][0], o[nt][1]);
            *(float2*)&po[(rloc + 8) * 64 + h] = make_float2(o[nt][2], o[nt][3]);
        }
        if ((lane & 3) == 0) {
            g_pm[pid * 64 + rloc]     = m0;
            g_pl[pid * 64 + rloc]     = l0;
            g_pm[pid * 64 + rloc + 8] = m1;
            g_pl[pid * 64 + rloc + 8] = l1;
        }
    }
}

// ---------------------------------------------------------------------------
// Kernel 3: merge split-KV partials (exact LSE merge).
// Grid (32, NB), 128 threads; thread handles one row-half (32 cols).
// ---------------------------------------------------------------------------
__global__ void merge_kernel(float* __restrict__ out)
{
    const int tq = 32 + blockIdx.x;
    const int b  = blockIdx.y;
    const int p0 = ((b * 32) + (tq - 32)) * 2;
    const int p1 = p0 + 1;
    const int t  = threadIdx.x;
    const int r  = t >> 1;
    const int c0 = (t & 1) * 32;

    float mA = g_pm[p0 * 64 + r], lA = g_pl[p0 * 64 + r];
    float mB = g_pm[p1 * 64 + r], lB = g_pl[p1 * 64 + r];
    float mf = fmaxf(mA, mB);
    float a0 = __expf(mA - mf), a1 = __expf(mB - mf);
    float inv = 1.0f / (a0 * lA + a1 * lB);
    a0 *= inv;  a1 *= inv;

    const float* o0 = g_po + (size_t)p0 * 4096 + r * 64 + c0;
    const float* o1 = g_po + (size_t)p1 * 4096 + r * 64 + c0;
    float* dst = out + (size_t)(b * TT + tq * 64 + r) * HD + c0;
    #pragma unroll
    for (int c = 0; c < 32; c += 4) {
        float4 x0 = *(const float4*)(o0 + c);
        float4 x1 = *(const float4*)(o1 + c);
        float4 w;
        w.x = a0 * x0.x + a1 * x1.x;
        w.y = a0 * x0.y + a1 * x1.y;
        w.z = a0 * x0.z + a1 * x1.z;
        w.w = a0 * x0.w + a1 * x1.w;
        *(float4*)(dst + c) = w;
    }
}

extern "C" void kernel_launch(void* const* d_in, const int* in_sizes, int n_in,
                              void* d_out, int out_size)
{
    const float* x  = (const float*)d_in[0];
    const float* Wk = (const float*)d_in[1];
    const float* Wq = (const float*)d_in[2];
    const float* Wv = (const float*)d_in[3];
    float* out = (float*)d_out;

    cudaFuncSetAttribute(proj_kernel, cudaFuncAttributeMaxDynamicSharedMemorySize, P_SMEM);
    cudaFuncSetAttribute(attn3_kernel, cudaFuncAttributeMaxDynamicSharedMemorySize, A_SMEM);

    wconv_kernel<<<192, 256>>>(Wk, Wq, Wv);
    proj_kernel<<<BT / 128, 256, P_SMEM>>>(x);
    attn3_kernel<<<dim3(96, NB), 128, A_SMEM>>>(out);
    merge_kernel<<<dim3(32, NB), 128>>>(out);
}